// round 8
// baseline (speedup 1.0000x reference)
#include <cuda_runtime.h>
#include <cstdint>

#define NMAX 50000
#define EMAX 800000

// ---------------- scratch (device globals: no runtime allocation) -------------
__device__ float g_hA[NMAX * 64];   // layer-0 output / layer-1 input
__device__ float g_Q[NMAX * 64];
__device__ float g_K[NMAX * 64];
__device__ float g_V[NMAX * 64];
__device__ float g_wV[NMAX * 64];
__device__ float g_Z[NMAX * 4];
__device__ float g_h1[NMAX * 64];

// ---------------- helpers ----------------------------------------------------
__device__ __forceinline__ void red_add_v4(float* addr, float a, float b, float c, float d) {
    asm volatile("red.global.add.v4.f32 [%0], {%1,%2,%3,%4};"
                 :: "l"(addr), "f"(a), "f"(b), "f"(c), "f"(d) : "memory");
}

__device__ __forceinline__ uint32_t f2tf32(float x) {
    uint32_t r; asm("cvt.rna.tf32.f32 %0, %1;" : "=r"(r) : "f"(x)); return r;
}

// split v into tf32 hi + tf32 lo (stored as fp32 bit patterns)
__device__ __forceinline__ float2 tf32_split(float v) {
    uint32_t h = f2tf32(v);
    float hf = __uint_as_float(h);
    uint32_t l = f2tf32(v - hf);
    return make_float2(hf, __uint_as_float(l));
}

__device__ __forceinline__ void mma8(float c[4], const uint32_t a[4], const uint32_t b[2]) {
    asm("mma.sync.aligned.m16n8k8.row.col.f32.tf32.tf32.f32 "
        "{%0,%1,%2,%3}, {%4,%5,%6,%7}, {%8,%9}, {%0,%1,%2,%3};"
        : "+f"(c[0]), "+f"(c[1]), "+f"(c[2]), "+f"(c[3])
        : "r"(a[0]), "r"(a[1]), "r"(a[2]), "r"(a[3]), "r"(b[0]), "r"(b[1]));
}

// 64x64x64 GEMM chunk on tensor cores, operands pre-split hi/lo in smem.
// A2: [64][AP] float2 (row, k).  W2: [AP2=68][...] float2 (k, n), pitch WP.
// Warp computes C[r0:r0+16][n0:n0+32] into acc[4][4].
// C map: C[r0+g+8*ci][n0+nt*8+t4*2+cj] = acc[nt][ci*2+cj], g=lane>>2, t4=lane&3.
template<int AP, int WP>
__device__ __forceinline__ void gemm64_hl(const float2* A2, const float2* W2,
                                          float acc[4][4], int r0, int n0) {
    int lane = threadIdx.x & 31;
    int g = lane >> 2, t4 = lane & 3;
#pragma unroll
    for (int k0 = 0; k0 < 64; k0 += 8) {
        float2 a0 = A2[(r0 + g)     * AP + k0 + t4];
        float2 a1 = A2[(r0 + g + 8) * AP + k0 + t4];
        float2 a2 = A2[(r0 + g)     * AP + k0 + t4 + 4];
        float2 a3 = A2[(r0 + g + 8) * AP + k0 + t4 + 4];
        uint32_t ah[4] = { __float_as_uint(a0.x), __float_as_uint(a1.x),
                           __float_as_uint(a2.x), __float_as_uint(a3.x) };
        uint32_t al[4] = { __float_as_uint(a0.y), __float_as_uint(a1.y),
                           __float_as_uint(a2.y), __float_as_uint(a3.y) };
#pragma unroll
        for (int nt = 0; nt < 4; ++nt) {
            int nn = n0 + nt * 8 + g;
            float2 b0 = W2[(k0 + t4)     * WP + nn];
            float2 b1 = W2[(k0 + t4 + 4) * WP + nn];
            uint32_t bh[2] = { __float_as_uint(b0.x), __float_as_uint(b1.x) };
            uint32_t bl[2] = { __float_as_uint(b0.y), __float_as_uint(b1.y) };
            mma8(acc[nt], ah, bh);
            mma8(acc[nt], ah, bl);
            mma8(acc[nt], al, bh);
        }
    }
}

// ================= fused QKV GEMM + wV/Z zeroing ==============================
__global__ void qkvz_kernel(const float* __restrict__ A,
                            const float* __restrict__ WQ,
                            const float* __restrict__ WK,
                            const float* __restrict__ WV, int n) {
    __shared__ float2 As2[64 * 68];
    __shared__ float2 Ws2[64 * 68];
    int row0 = blockIdx.x * 64;
    int tid = threadIdx.x;
    int w = tid >> 5, lane = tid & 31;
    int g = lane >> 2, t4 = lane & 3;
    int r0 = (w & 3) * 16, n0 = (w >> 2) * 32;

    // zero wV / Z for this block's row range
    for (int i = tid; i < 4096; i += 256) {
        int idx = row0 * 64 + i;
        if (idx < n * 64) g_wV[idx] = 0.f;
    }
    {
        int idx = row0 * 4 + tid;
        if (idx < n * 4) g_Z[idx] = 0.f;
    }

    for (int i = tid; i < 4096; i += 256) {
        int r = i >> 6, c = i & 63;
        int gr = row0 + r;
        As2[r * 68 + c] = (gr < n) ? tf32_split(A[(size_t)gr * 64 + c])
                                   : make_float2(0.f, 0.f);
    }

#pragma unroll
    for (int p = 0; p < 3; ++p) {
        const float* W = (p == 0) ? WQ : (p == 1) ? WK : WV;
        float* C = (p == 0) ? g_Q : (p == 1) ? g_K : g_V;
        __syncthreads();   // As2 ready (p=0) / previous Ws2 reads done (p>0)
        for (int i = tid; i < 4096; i += 256)
            Ws2[(i >> 6) * 68 + (i & 63)] = tf32_split(W[i]);
        __syncthreads();

        float acc[4][4] = {};
        gemm64_hl<68, 68>(As2, Ws2, acc, r0, n0);

#pragma unroll
        for (int nt = 0; nt < 4; ++nt) {
            int col = n0 + nt * 8 + t4 * 2;
#pragma unroll
            for (int ci = 0; ci < 2; ++ci) {
                int gr = row0 + r0 + g + 8 * ci;
                if (gr < n) {
                    float2 o = make_float2(acc[nt][ci * 2], acc[nt][ci * 2 + 1]);
                    *(float2*)&C[(size_t)gr * 64 + col] = o;
                }
            }
        }
    }
}

// ================= fused edge kernel ==========================================
__global__ void edge_kernel(const float* __restrict__ Ae, const float* __restrict__ WE,
                            const int* __restrict__ ei, int ne) {
    __shared__ float2 As2[64 * 68];   // edge_attr hi/lo, then reused as float Eh
    __shared__ float2 Ws2[64 * 68];   // WE hi/lo
    __shared__ int s_src[64], s_dst[64];
    int e0 = blockIdx.x * 64;
    int tid = threadIdx.x;
    int w = tid >> 5, lane = tid & 31;
    int g = lane >> 2, t4 = lane & 3;
    int r0 = (w & 3) * 16, n0 = (w >> 2) * 32;

    for (int i = tid; i < 4096; i += 256)
        Ws2[(i >> 6) * 68 + (i & 63)] = tf32_split(WE[i]);
    for (int i = tid; i < 4096; i += 256) {
        int e = i >> 6, c = i & 63;
        int ge = e0 + e;
        As2[e * 68 + c] = (ge < ne) ? tf32_split(Ae[(size_t)ge * 64 + c])
                                    : make_float2(0.f, 0.f);
    }
    if (tid < 64) {
        int ge = e0 + tid;
        s_src[tid] = (ge < ne) ? ei[ge] : 0;
        s_dst[tid] = (ge < ne) ? ei[ne + ge] : 0;
    }
    __syncthreads();

    float acc[4][4] = {};
    gemm64_hl<68, 68>(As2, Ws2, acc, r0, n0);
    __syncthreads();   // As2 reads done; reuse its storage for Eh floats

    float* Ehs = (float*)As2;   // [64][68] floats
#pragma unroll
    for (int nt = 0; nt < 4; ++nt) {
        int col = n0 + nt * 8 + t4 * 2;
#pragma unroll
        for (int ci = 0; ci < 2; ++ci) {
            Ehs[(r0 + g + 8 * ci) * 68 + col]     = acc[nt][ci * 2];
            Ehs[(r0 + g + 8 * ci) * 68 + col + 1] = acc[nt][ci * 2 + 1];
        }
    }
    __syncthreads();

    // phase 2: one thread per (edge, head)
    int e = tid >> 2, h = tid & 3;
    int ge = e0 + e;
    if (ge < ne) {
        int sn = s_src[e], dn = s_dst[e];
        const float4* Kp = (const float4*)(g_K + (size_t)sn * 64 + h * 16);
        const float4* Qp = (const float4*)(g_Q + (size_t)dn * 64 + h * 16);
        float s = 0.f;
#pragma unroll
        for (int i = 0; i < 4; ++i) {
            float4 k4 = Kp[i];
            float4 q4 = Qp[i];
            const float* ep = &Ehs[e * 68 + h * 16 + i * 4];
            s += k4.x * q4.x * ep[0] + k4.y * q4.y * ep[1] +
                 k4.z * q4.z * ep[2] + k4.w * q4.w * ep[3];
        }
        s *= 0.25f;                        // 1/sqrt(16)
        s = fminf(fmaxf(s, -5.f), 5.f);
        float sc = __expf(s);
        atomicAdd(&g_Z[(size_t)dn * 4 + h], sc);
        const float4* Vp = (const float4*)(g_V + (size_t)sn * 64 + h * 16);
        float* wp = g_wV + (size_t)dn * 64 + h * 16;
#pragma unroll
        for (int i = 0; i < 4; ++i) {
            float4 v = Vp[i];
            red_add_v4(wp + i * 4, v.x * sc, v.y * sc, v.z * sc, v.w * sc);
        }
    }
}

// ================= attn out-proj + residual + LayerNorm1 ======================
__global__ void attn_ln_kernel(const float* __restrict__ WO, const float* __restrict__ bO,
                               const float* __restrict__ g1, const float* __restrict__ be,
                               const float* __restrict__ hin, int n) {
    __shared__ float2 As2[64 * 68];   // wV/Z hi/lo, then reused as float t
    __shared__ float2 Ws2[64 * 68];
    int row0 = blockIdx.x * 64;
    int tid = threadIdx.x;
    int w = tid >> 5, lane = tid & 31;
    int g = lane >> 2, t4 = lane & 3;
    int r0 = (w & 3) * 16, n0 = (w >> 2) * 32;

    for (int i = tid; i < 4096; i += 256)
        Ws2[(i >> 6) * 68 + (i & 63)] = tf32_split(WO[i]);
    for (int i = tid; i < 4096; i += 256) {
        int r = i >> 6, c = i & 63;
        int gr = row0 + r;
        if (gr < n) {
            float z = g_Z[(size_t)gr * 4 + (c >> 4)] + 1e-6f;
            As2[r * 68 + c] = tf32_split(g_wV[(size_t)gr * 64 + c] / z);
        } else {
            As2[r * 68 + c] = make_float2(0.f, 0.f);
        }
    }
    __syncthreads();

    float acc[4][4] = {};
    gemm64_hl<68, 68>(As2, Ws2, acc, r0, n0);
    __syncthreads();   // reuse As2 storage for t floats

    float* ts = (float*)As2;   // [64][68]
#pragma unroll
    for (int nt = 0; nt < 4; ++nt) {
        int col = n0 + nt * 8 + t4 * 2;
        float2 bb = *(const float2*)&bO[col];
#pragma unroll
        for (int ci = 0; ci < 2; ++ci) {
            int r = r0 + g + 8 * ci;
            int gr = row0 + r;
            if (gr < n) {
                float2 h4 = *(const float2*)&hin[(size_t)gr * 64 + col];
                ts[r * 68 + col]     = h4.x + acc[nt][ci * 2]     + bb.x;
                ts[r * 68 + col + 1] = h4.y + acc[nt][ci * 2 + 1] + bb.y;
            }
        }
    }
    __syncthreads();

    // LayerNorm: 8 warps x 8 rows
    for (int i = 0; i < 8; ++i) {
        int r = w * 8 + i;
        int gr = row0 + r;
        if (gr >= n) break;
        float x0 = ts[r * 68 + lane], x1 = ts[r * 68 + lane + 32];
        float s = x0 + x1;
#pragma unroll
        for (int o = 16; o; o >>= 1) s += __shfl_xor_sync(0xffffffffu, s, o);
        float mu = s * (1.f / 64.f);
        float d0 = x0 - mu, d1 = x1 - mu;
        float v = d0 * d0 + d1 * d1;
#pragma unroll
        for (int o = 16; o; o >>= 1) v += __shfl_xor_sync(0xffffffffu, v, o);
        float inv = rsqrtf(v * (1.f / 64.f) + 1e-5f);
        g_h1[(size_t)gr * 64 + lane]      = d0 * inv * g1[lane] + be[lane];
        g_h1[(size_t)gr * 64 + lane + 32] = d1 * inv * g1[lane + 32] + be[lane + 32];
    }
}

// ================= fused FFN (W1+relu, W2) + residual + LayerNorm2 ============
// hout = LN(h1 + relu(h1 @ W1 + b1) @ W2 + b2)
// GEMM1 half-kk produces u-half; immediately consumed by GEMM2 chunk-kk.
__global__ void ffn_ln_kernel(const float* __restrict__ W1, const float* __restrict__ b1,
                              const float* __restrict__ W2, const float* __restrict__ b2,
                              const float* __restrict__ g1, const float* __restrict__ be,
                              float* __restrict__ hout, int n) {
    __shared__ float2 h1s2[64 * 68];  // h1 hi/lo
    __shared__ float2 Us2[64 * 68];   // current u-half hi/lo, later float t
    __shared__ float2 Ws2[64 * 68];
    int row0 = blockIdx.x * 64;
    int tid = threadIdx.x;
    int w = tid >> 5, lane = tid & 31;
    int g = lane >> 2, t4 = lane & 3;
    int r0 = (w & 3) * 16, n0 = (w >> 2) * 32;

    for (int i = tid; i < 4096; i += 256) {
        int r = i >> 6, c = i & 63;
        int gr = row0 + r;
        h1s2[r * 68 + c] = (gr < n) ? tf32_split(g_h1[(size_t)gr * 64 + c])
                                    : make_float2(0.f, 0.f);
    }

    float acc2[4][4] = {};
#pragma unroll
    for (int kk = 0; kk < 2; ++kk) {
        __syncthreads();   // h1s2 ready / prior-iter Ws2+Us2 reads done
        for (int i = tid; i < 4096; i += 256)
            Ws2[(i >> 6) * 68 + (i & 63)] =
                tf32_split(W1[(size_t)(i >> 6) * 128 + kk * 64 + (i & 63)]);
        __syncthreads();

        // GEMM1 half: u[:, kk*64 + (0..63)]
        float acc[4][4] = {};
        gemm64_hl<68, 68>(h1s2, Ws2, acc, r0, n0);

        // write relu(u) hi/lo into Us2 (each cell written by exactly one thread)
#pragma unroll
        for (int nt = 0; nt < 4; ++nt) {
            int col = n0 + nt * 8 + t4 * 2;
            float2 bb = *(const float2*)&b1[kk * 64 + col];
#pragma unroll
            for (int ci = 0; ci < 2; ++ci) {
                int r = r0 + g + 8 * ci;
                Us2[r * 68 + col]     = tf32_split(fmaxf(acc[nt][ci * 2]     + bb.x, 0.f));
                Us2[r * 68 + col + 1] = tf32_split(fmaxf(acc[nt][ci * 2 + 1] + bb.y, 0.f));
            }
        }
        __syncthreads();   // Us2 complete; Ws2 gemm1 reads done
        for (int i = tid; i < 4096; i += 256)
            Ws2[(i >> 6) * 68 + (i & 63)] =
                tf32_split(W2[(size_t)(kk * 64 + (i >> 6)) * 64 + (i & 63)]);
        __syncthreads();

        // GEMM2 chunk: acc2 += u_half @ W2[kk*64:...]
        gemm64_hl<68, 68>(Us2, Ws2, acc2, r0, n0);
    }
    __syncthreads();   // Us2 reads done; reuse as float t

    float* ts = (float*)Us2;   // [64][68]
#pragma unroll
    for (int nt = 0; nt < 4; ++nt) {
        int col = n0 + nt * 8 + t4 * 2;
        float2 bb = *(const float2*)&b2[col];
#pragma unroll
        for (int ci = 0; ci < 2; ++ci) {
            int r = r0 + g + 8 * ci;
            float2 hh0 = h1s2[r * 68 + col];
            float2 hh1 = h1s2[r * 68 + col + 1];
            ts[r * 68 + col]     = (hh0.x + hh0.y) + acc2[nt][ci * 2]     + bb.x;
            ts[r * 68 + col + 1] = (hh1.x + hh1.y) + acc2[nt][ci * 2 + 1] + bb.y;
        }
    }
    __syncthreads();

    // LayerNorm2: 8 warps x 8 rows
    for (int i = 0; i < 8; ++i) {
        int r = w * 8 + i;
        int gr = row0 + r;
        if (gr >= n) break;
        float x0 = ts[r * 68 + lane], x1 = ts[r * 68 + lane + 32];
        float s = x0 + x1;
#pragma unroll
        for (int o = 16; o; o >>= 1) s += __shfl_xor_sync(0xffffffffu, s, o);
        float mu = s * (1.f / 64.f);
        float d0 = x0 - mu, d1 = x1 - mu;
        float v = d0 * d0 + d1 * d1;
#pragma unroll
        for (int o = 16; o; o >>= 1) v += __shfl_xor_sync(0xffffffffu, v, o);
        float inv = rsqrtf(v * (1.f / 64.f) + 1e-5f);
        hout[(size_t)gr * 64 + lane]      = d0 * inv * g1[lane] + be[lane];
        hout[(size_t)gr * 64 + lane + 32] = d1 * inv * g1[lane + 32] + be[lane + 32];
    }
}

// ---------------- host orchestration ------------------------------------------
extern "C" void kernel_launch(void* const* d_in, const int* in_sizes, int n_in,
                              void* d_out, int out_size) {
    const float* x   = (const float*)d_in[0];
    const float* ea  = (const float*)d_in[1];
    const int*   ei  = (const int*)d_in[2];   // int32 per harness dtype rules
    const float* WQ  = (const float*)d_in[3];
    const float* WK  = (const float*)d_in[4];
    const float* WE  = (const float*)d_in[5];
    const float* WV  = (const float*)d_in[6];
    const float* WO  = (const float*)d_in[7];
    const float* bO  = (const float*)d_in[8];
    const float* g1  = (const float*)d_in[9];
    const float* be1 = (const float*)d_in[10];
    const float* W1  = (const float*)d_in[11];
    const float* b1  = (const float*)d_in[12];
    const float* W2  = (const float*)d_in[13];
    const float* b2  = (const float*)d_in[14];
    const float* g2  = (const float*)d_in[15];
    const float* be2 = (const float*)d_in[16];
    float* out = (float*)d_out;

    int n  = in_sizes[0] / 64;
    int ne = in_sizes[2] / 2;

    float* p_hA;
    cudaGetSymbolAddress((void**)&p_hA, g_hA);

    int nb64 = (n + 63) / 64;
    int nbe  = (ne + 63) / 64;

    for (int l = 0; l < 2; ++l) {
        const float* hin  = l ? p_hA : x;
        float*       hout = l ? out : p_hA;
        size_t wo  = (size_t)l * 64 * 64;
        size_t wo1 = (size_t)l * 64 * 128;
        size_t bo  = (size_t)l * 64;
        size_t bo1 = (size_t)l * 128;

        qkvz_kernel<<<nb64, 256>>>(hin, WQ + wo, WK + wo, WV + wo, n);
        edge_kernel<<<nbe, 256>>>(ea, WE + wo, ei, ne);
        attn_ln_kernel<<<nb64, 256>>>(WO + wo, bO + bo, g1 + bo, be1 + bo, hin, n);
        ffn_ln_kernel<<<nb64, 256>>>(W1 + wo1, b1 + bo1, W2 + wo1, b2 + bo,
                                     g2 + bo, be2 + bo, hout, n);
    }
}

// round 9
// speedup vs baseline: 1.9853x; 1.9853x over previous
#include <cuda_runtime.h>
#include <cuda_bf16.h>
#include <cstdint>

#define NMAX 50000
#define EMAX 800000

// ---------------- scratch (device globals: no runtime allocation) -------------
__device__ float g_hA[NMAX * 64];   // layer-0 output / layer-1 input
__device__ float g_Q[NMAX * 64];
__device__ float g_K[NMAX * 64];
__device__ float g_V[NMAX * 64];
__device__ float g_wV[NMAX * 64];
__device__ float g_Z[NMAX * 4];
__device__ float g_h1[NMAX * 64];

// ---------------- helpers ----------------------------------------------------
__device__ __forceinline__ void red_add_v4(float* addr, float a, float b, float c, float d) {
    asm volatile("red.global.add.v4.f32 [%0], {%1,%2,%3,%4};"
                 :: "l"(addr), "f"(a), "f"(b), "f"(c), "f"(d) : "memory");
}

// split (x,y) into packed bf16x2 hi word + lo word; store to planes at idx
__device__ __forceinline__ void split_store(uint32_t* hi, uint32_t* lo, int idx,
                                            float x, float y) {
    __nv_bfloat162 h = __floats2bfloat162_rn(x, y);
    float hx = __bfloat162float(h.x);
    float hy = __bfloat162float(h.y);
    __nv_bfloat162 l = __floats2bfloat162_rn(x - hx, y - hy);
    hi[idx] = *reinterpret_cast<uint32_t*>(&h);
    lo[idx] = *reinterpret_cast<uint32_t*>(&l);
}

__device__ __forceinline__ void mma16(float c[4], const uint32_t a[4], const uint32_t b[2]) {
    asm("mma.sync.aligned.m16n8k16.row.col.f32.bf16.bf16.f32 "
        "{%0,%1,%2,%3}, {%4,%5,%6,%7}, {%8,%9}, {%0,%1,%2,%3};"
        : "+f"(c[0]), "+f"(c[1]), "+f"(c[2]), "+f"(c[3])
        : "r"(a[0]), "r"(a[1]), "r"(a[2]), "r"(a[3]), "r"(b[0]), "r"(b[1]));
}

// 64x64x64 GEMM on tensor cores, bf16 3-term split, operands pre-split in smem.
// A planes: [rows][AP] uint32 k-pairs (row-major).  W planes: [32 kp][WP] (k-major).
// Warp computes C[r0:r0+16][n0:n0+32] -> acc[4][4].
// C map: C[r0+g+8*ci][n0+nt*8+t4*2+cj] = acc[nt][ci*2+cj], g=lane>>2, t4=lane&3.
template<int AP, int WP>
__device__ __forceinline__ void gemm64_bf16(const uint32_t* __restrict__ Ahi,
                                            const uint32_t* __restrict__ Alo,
                                            const uint32_t* __restrict__ Whi,
                                            const uint32_t* __restrict__ Wlo,
                                            float acc[4][4], int r0, int n0) {
    int lane = threadIdx.x & 31;
    int g = lane >> 2, t4 = lane & 3;
#pragma unroll
    for (int kb = 0; kb < 32; kb += 8) {   // k-pair base: 4 steps of k=16
        int ia0 = (r0 + g) * AP + kb + t4;
        int ia1 = (r0 + g + 8) * AP + kb + t4;
        uint32_t ah[4] = { Ahi[ia0], Ahi[ia1], Ahi[ia0 + 4], Ahi[ia1 + 4] };
        uint32_t al[4] = { Alo[ia0], Alo[ia1], Alo[ia0 + 4], Alo[ia1 + 4] };
#pragma unroll
        for (int nt = 0; nt < 4; ++nt) {
            int nn = n0 + nt * 8 + g;
            int ib0 = (kb + t4) * WP + nn;
            int ib1 = (kb + t4 + 4) * WP + nn;
            uint32_t bh[2] = { Whi[ib0], Whi[ib1] };
            uint32_t bl[2] = { Wlo[ib0], Wlo[ib1] };
            mma16(acc[nt], ah, bh);
            mma16(acc[nt], ah, bl);
            mma16(acc[nt], al, bh);
        }
    }
}

// smem word offsets (uint32 units)
#define A_HI 0
#define A_LO 2304      // 64*36
#define W_HI 4608
#define W_LO 6912      // + 32*72
#define SM_WORDS 9216

// ================= fused QKV GEMM + wV/Z zeroing ==============================
__global__ void qkvz_kernel(const float* __restrict__ A,
                            const float* __restrict__ WQ,
                            const float* __restrict__ WK,
                            const float* __restrict__ WV, int n) {
    __shared__ uint32_t sm[SM_WORDS];
    int row0 = blockIdx.x * 64;
    int tid = threadIdx.x;
    int w = tid >> 5, lane = tid & 31;
    int g = lane >> 2, t4 = lane & 3;
    int r0 = (w & 3) * 16, n0 = (w >> 2) * 32;

    // zero wV / Z for this block's row range
    for (int i = tid; i < 4096; i += 256) {
        int idx = row0 * 64 + i;
        if (idx < n * 64) g_wV[idx] = 0.f;
    }
    {
        int idx = row0 * 4 + tid;
        if (idx < n * 4) g_Z[idx] = 0.f;
    }

    // load + split A tile (2048 k-pairs)
    for (int i = tid; i < 2048; i += 256) {
        int r = i >> 5, kp = i & 31;
        int gr = row0 + r;
        float2 v = (gr < n) ? *(const float2*)&A[(size_t)gr * 64 + kp * 2]
                            : make_float2(0.f, 0.f);
        split_store(sm + A_HI, sm + A_LO, r * 36 + kp, v.x, v.y);
    }

#pragma unroll
    for (int p = 0; p < 3; ++p) {
        const float* W = (p == 0) ? WQ : (p == 1) ? WK : WV;
        float* C = (p == 0) ? g_Q : (p == 1) ? g_K : g_V;
        __syncthreads();   // A ready (p=0) / previous W reads done (p>0)
        for (int i = tid; i < 2048; i += 256) {
            int kp = i >> 6, nn = i & 63;
            split_store(sm + W_HI, sm + W_LO, kp * 72 + nn,
                        W[(size_t)(2 * kp) * 64 + nn], W[(size_t)(2 * kp + 1) * 64 + nn]);
        }
        __syncthreads();

        float acc[4][4] = {};
        gemm64_bf16<36, 72>(sm + A_HI, sm + A_LO, sm + W_HI, sm + W_LO, acc, r0, n0);

#pragma unroll
        for (int nt = 0; nt < 4; ++nt) {
            int col = n0 + nt * 8 + t4 * 2;
#pragma unroll
            for (int ci = 0; ci < 2; ++ci) {
                int gr = row0 + r0 + g + 8 * ci;
                if (gr < n) {
                    float2 o = make_float2(acc[nt][ci * 2], acc[nt][ci * 2 + 1]);
                    *(float2*)&C[(size_t)gr * 64 + col] = o;
                }
            }
        }
    }
}

// ================= fused edge kernel ==========================================
__global__ void edge_kernel(const float* __restrict__ Ae, const float* __restrict__ WE,
                            const int* __restrict__ ei, int ne) {
    __shared__ uint32_t sm[SM_WORDS];
    __shared__ int s_src[64], s_dst[64];
    int e0 = blockIdx.x * 64;
    int tid = threadIdx.x;
    int w = tid >> 5, lane = tid & 31;
    int g = lane >> 2, t4 = lane & 3;
    int r0 = (w & 3) * 16, n0 = (w >> 2) * 32;

    for (int i = tid; i < 2048; i += 256) {
        int kp = i >> 6, nn = i & 63;
        split_store(sm + W_HI, sm + W_LO, kp * 72 + nn,
                    WE[(size_t)(2 * kp) * 64 + nn], WE[(size_t)(2 * kp + 1) * 64 + nn]);
    }
    for (int i = tid; i < 2048; i += 256) {
        int e = i >> 5, kp = i & 31;
        int ge = e0 + e;
        float2 v = (ge < ne) ? *(const float2*)&Ae[(size_t)ge * 64 + kp * 2]
                             : make_float2(0.f, 0.f);
        split_store(sm + A_HI, sm + A_LO, e * 36 + kp, v.x, v.y);
    }
    if (tid < 64) {
        int ge = e0 + tid;
        s_src[tid] = (ge < ne) ? ei[ge] : 0;
        s_dst[tid] = (ge < ne) ? ei[ne + ge] : 0;
    }
    __syncthreads();

    float acc[4][4] = {};
    gemm64_bf16<36, 72>(sm + A_HI, sm + A_LO, sm + W_HI, sm + W_LO, acc, r0, n0);
    __syncthreads();   // all A-plane reads done; reuse that space for Eh floats

    float* Ehs = (float*)(sm + A_HI);   // [64][68] floats (4352 <= 4608 words)
#pragma unroll
    for (int nt = 0; nt < 4; ++nt) {
        int col = n0 + nt * 8 + t4 * 2;
#pragma unroll
        for (int ci = 0; ci < 2; ++ci) {
            Ehs[(r0 + g + 8 * ci) * 68 + col]     = acc[nt][ci * 2];
            Ehs[(r0 + g + 8 * ci) * 68 + col + 1] = acc[nt][ci * 2 + 1];
        }
    }
    __syncthreads();

    // phase 2: one thread per (edge, head)
    int e = tid >> 2, h = tid & 3;
    int ge = e0 + e;
    if (ge < ne) {
        int sn = s_src[e], dn = s_dst[e];
        const float4* Kp = (const float4*)(g_K + (size_t)sn * 64 + h * 16);
        const float4* Qp = (const float4*)(g_Q + (size_t)dn * 64 + h * 16);
        float s = 0.f;
#pragma unroll
        for (int i = 0; i < 4; ++i) {
            float4 k4 = Kp[i];
            float4 q4 = Qp[i];
            const float* ep = &Ehs[e * 68 + h * 16 + i * 4];
            s += k4.x * q4.x * ep[0] + k4.y * q4.y * ep[1] +
                 k4.z * q4.z * ep[2] + k4.w * q4.w * ep[3];
        }
        s *= 0.25f;                        // 1/sqrt(16)
        s = fminf(fmaxf(s, -5.f), 5.f);
        float sc = __expf(s);
        atomicAdd(&g_Z[(size_t)dn * 4 + h], sc);
        const float4* Vp = (const float4*)(g_V + (size_t)sn * 64 + h * 16);
        float* wp = g_wV + (size_t)dn * 64 + h * 16;
#pragma unroll
        for (int i = 0; i < 4; ++i) {
            float4 v = Vp[i];
            red_add_v4(wp + i * 4, v.x * sc, v.y * sc, v.z * sc, v.w * sc);
        }
    }
}

// ================= attn out-proj + residual + LayerNorm1 ======================
__global__ void attn_ln_kernel(const float* __restrict__ WO, const float* __restrict__ bO,
                               const float* __restrict__ g1, const float* __restrict__ be,
                               const float* __restrict__ hin, int n) {
    __shared__ uint32_t sm[SM_WORDS];
    int row0 = blockIdx.x * 64;
    int tid = threadIdx.x;
    int w = tid >> 5, lane = tid & 31;
    int g = lane >> 2, t4 = lane & 3;
    int r0 = (w & 3) * 16, n0 = (w >> 2) * 32;

    for (int i = tid; i < 2048; i += 256) {
        int kp = i >> 6, nn = i & 63;
        split_store(sm + W_HI, sm + W_LO, kp * 72 + nn,
                    WO[(size_t)(2 * kp) * 64 + nn], WO[(size_t)(2 * kp + 1) * 64 + nn]);
    }
    for (int i = tid; i < 2048; i += 256) {
        int r = i >> 5, kp = i & 31;
        int gr = row0 + r;
        float vx = 0.f, vy = 0.f;
        if (gr < n) {
            float z = g_Z[(size_t)gr * 4 + (kp >> 3)] + 1e-6f;   // head = (kp*2)>>4
            float2 v = *(const float2*)&g_wV[(size_t)gr * 64 + kp * 2];
            vx = v.x / z; vy = v.y / z;
        }
        split_store(sm + A_HI, sm + A_LO, r * 36 + kp, vx, vy);
    }
    __syncthreads();

    float acc[4][4] = {};
    gemm64_bf16<36, 72>(sm + A_HI, sm + A_LO, sm + W_HI, sm + W_LO, acc, r0, n0);
    __syncthreads();   // reuse A-plane space for t floats

    float* ts = (float*)(sm + A_HI);   // [64][68]
#pragma unroll
    for (int nt = 0; nt < 4; ++nt) {
        int col = n0 + nt * 8 + t4 * 2;
        float2 bb = *(const float2*)&bO[col];
#pragma unroll
        for (int ci = 0; ci < 2; ++ci) {
            int r = r0 + g + 8 * ci;
            int gr = row0 + r;
            if (gr < n) {
                float2 h4 = *(const float2*)&hin[(size_t)gr * 64 + col];
                ts[r * 68 + col]     = h4.x + acc[nt][ci * 2]     + bb.x;
                ts[r * 68 + col + 1] = h4.y + acc[nt][ci * 2 + 1] + bb.y;
            }
        }
    }
    __syncthreads();

    // LayerNorm: 8 warps x 8 rows
    for (int i = 0; i < 8; ++i) {
        int r = w * 8 + i;
        int gr = row0 + r;
        if (gr >= n) break;
        float x0 = ts[r * 68 + lane], x1 = ts[r * 68 + lane + 32];
        float s = x0 + x1;
#pragma unroll
        for (int o = 16; o; o >>= 1) s += __shfl_xor_sync(0xffffffffu, s, o);
        float mu = s * (1.f / 64.f);
        float d0 = x0 - mu, d1 = x1 - mu;
        float v = d0 * d0 + d1 * d1;
#pragma unroll
        for (int o = 16; o; o >>= 1) v += __shfl_xor_sync(0xffffffffu, v, o);
        float inv = rsqrtf(v * (1.f / 64.f) + 1e-5f);
        g_h1[(size_t)gr * 64 + lane]      = d0 * inv * g1[lane] + be[lane];
        g_h1[(size_t)gr * 64 + lane + 32] = d1 * inv * g1[lane + 32] + be[lane + 32];
    }
}

// ================= fused FFN (W1+relu, W2) + residual + LayerNorm2 ============
// hout = LN(h1 + relu(h1 @ W1 + b1) @ W2 + b2)
// kk-chunked: GEMM1 half -> u-half planes -> GEMM2 chunk accumulates.
__global__ void ffn_ln_kernel(const float* __restrict__ W1, const float* __restrict__ b1,
                              const float* __restrict__ W2, const float* __restrict__ b2,
                              const float* __restrict__ g1, const float* __restrict__ be,
                              float* __restrict__ hout, int n) {
    __shared__ uint32_t sm[13824];
    // offsets: h1 planes [0,4608), U-half planes [4608,9216), W planes [9216,13824)
    uint32_t* H_HIp = sm;
    uint32_t* H_LOp = sm + 2304;
    uint32_t* U_HIp = sm + 4608;
    uint32_t* U_LOp = sm + 6912;
    uint32_t* Wk_HI = sm + 9216;
    uint32_t* Wk_LO = sm + 11520;
    int row0 = blockIdx.x * 64;
    int tid = threadIdx.x;
    int w = tid >> 5, lane = tid & 31;
    int g = lane >> 2, t4 = lane & 3;
    int r0 = (w & 3) * 16, n0 = (w >> 2) * 32;

    for (int i = tid; i < 2048; i += 256) {
        int r = i >> 5, kp = i & 31;
        int gr = row0 + r;
        float2 v = (gr < n) ? *(const float2*)&g_h1[(size_t)gr * 64 + kp * 2]
                            : make_float2(0.f, 0.f);
        split_store(H_HIp, H_LOp, r * 36 + kp, v.x, v.y);
    }

    float acc2[4][4] = {};
#pragma unroll
    for (int kk = 0; kk < 2; ++kk) {
        __syncthreads();   // h1 planes ready / prior-iter W+U reads done
        for (int i = tid; i < 2048; i += 256) {
            int kp = i >> 6, nn = i & 63;
            split_store(Wk_HI, Wk_LO, kp * 72 + nn,
                        W1[(size_t)(2 * kp) * 128 + kk * 64 + nn],
                        W1[(size_t)(2 * kp + 1) * 128 + kk * 64 + nn]);
        }
        __syncthreads();

        // GEMM1 half: u[:, kk*64 .. kk*64+63]
        float acc[4][4] = {};
        gemm64_bf16<36, 72>(H_HIp, H_LOp, Wk_HI, Wk_LO, acc, r0, n0);

        // relu + split into U-half planes (each k-pair written by one thread)
#pragma unroll
        for (int nt = 0; nt < 4; ++nt) {
            int col = n0 + nt * 8 + t4 * 2;          // within-half column (even)
            float2 bb = *(const float2*)&b1[kk * 64 + col];
            int cp = col >> 1;
#pragma unroll
            for (int ci = 0; ci < 2; ++ci) {
                int r = r0 + g + 8 * ci;
                float u0 = fmaxf(acc[nt][ci * 2]     + bb.x, 0.f);
                float u1 = fmaxf(acc[nt][ci * 2 + 1] + bb.y, 0.f);
                split_store(U_HIp, U_LOp, r * 36 + cp, u0, u1);
            }
        }
        __syncthreads();   // U-half complete; W1 reads done
        for (int i = tid; i < 2048; i += 256) {
            int kp = i >> 6, nn = i & 63;
            split_store(Wk_HI, Wk_LO, kp * 72 + nn,
                        W2[(size_t)(kk * 64 + 2 * kp) * 64 + nn],
                        W2[(size_t)(kk * 64 + 2 * kp + 1) * 64 + nn]);
        }
        __syncthreads();

        // GEMM2 chunk: acc2 += u_half @ W2[kk*64:kk*64+64, :]
        gemm64_bf16<36, 72>(U_HIp, U_LOp, Wk_HI, Wk_LO, acc2, r0, n0);
    }
    __syncthreads();   // U reads done; reuse U region for t floats

    float* ts = (float*)U_HIp;   // [64][68] floats (4352 <= 4608 words)
#pragma unroll
    for (int nt = 0; nt < 4; ++nt) {
        int col = n0 + nt * 8 + t4 * 2;
        float2 bb = *(const float2*)&b2[col];
        int cp = col >> 1;
#pragma unroll
        for (int ci = 0; ci < 2; ++ci) {
            int r = r0 + g + 8 * ci;
            uint32_t hw = H_HIp[r * 36 + cp], lw = H_LOp[r * 36 + cp];
            __nv_bfloat162 hh = *reinterpret_cast<__nv_bfloat162*>(&hw);
            __nv_bfloat162 ll = *reinterpret_cast<__nv_bfloat162*>(&lw);
            float h0 = __bfloat162float(hh.x) + __bfloat162float(ll.x);
            float h1v = __bfloat162float(hh.y) + __bfloat162float(ll.y);
            ts[r * 68 + col]     = h0  + acc2[nt][ci * 2]     + bb.x;
            ts[r * 68 + col + 1] = h1v + acc2[nt][ci * 2 + 1] + bb.y;
        }
    }
    __syncthreads();

    // LayerNorm2: 8 warps x 8 rows
    for (int i = 0; i < 8; ++i) {
        int r = w * 8 + i;
        int gr = row0 + r;
        if (gr >= n) break;
        float x0 = ts[r * 68 + lane], x1 = ts[r * 68 + lane + 32];
        float s = x0 + x1;
#pragma unroll
        for (int o = 16; o; o >>= 1) s += __shfl_xor_sync(0xffffffffu, s, o);
        float mu = s * (1.f / 64.f);
        float d0 = x0 - mu, d1 = x1 - mu;
        float v = d0 * d0 + d1 * d1;
#pragma unroll
        for (int o = 16; o; o >>= 1) v += __shfl_xor_sync(0xffffffffu, v, o);
        float inv = rsqrtf(v * (1.f / 64.f) + 1e-5f);
        hout[(size_t)gr * 64 + lane]      = d0 * inv * g1[lane] + be[lane];
        hout[(size_t)gr * 64 + lane + 32] = d1 * inv * g1[lane + 32] + be[lane + 32];
    }
}

// ---------------- host orchestration ------------------------------------------
extern "C" void kernel_launch(void* const* d_in, const int* in_sizes, int n_in,
                              void* d_out, int out_size) {
    const float* x   = (const float*)d_in[0];
    const float* ea  = (const float*)d_in[1];
    const int*   ei  = (const int*)d_in[2];   // int32 per harness dtype rules
    const float* WQ  = (const float*)d_in[3];
    const float* WK  = (const float*)d_in[4];
    const float* WE  = (const float*)d_in[5];
    const float* WV  = (const float*)d_in[6];
    const float* WO  = (const float*)d_in[7];
    const float* bO  = (const float*)d_in[8];
    const float* g1  = (const float*)d_in[9];
    const float* be1 = (const float*)d_in[10];
    const float* W1  = (const float*)d_in[11];
    const float* b1  = (const float*)d_in[12];
    const float* W2  = (const float*)d_in[13];
    const float* b2  = (const float*)d_in[14];
    const float* g2  = (const float*)d_in[15];
    const float* be2 = (const float*)d_in[16];
    float* out = (float*)d_out;

    int n  = in_sizes[0] / 64;
    int ne = in_sizes[2] / 2;

    float* p_hA;
    cudaGetSymbolAddress((void**)&p_hA, g_hA);

    int nb64 = (n + 63) / 64;
    int nbe  = (ne + 63) / 64;

    for (int l = 0; l < 2; ++l) {
        const float* hin  = l ? p_hA : x;
        float*       hout = l ? out : p_hA;
        size_t wo  = (size_t)l * 64 * 64;
        size_t wo1 = (size_t)l * 64 * 128;
        size_t bo  = (size_t)l * 64;
        size_t bo1 = (size_t)l * 128;

        qkvz_kernel<<<nb64, 256>>>(hin, WQ + wo, WK + wo, WV + wo, n);
        edge_kernel<<<nbe, 256>>>(ea, WE + wo, ei, ne);
        attn_ln_kernel<<<nb64, 256>>>(WO + wo, bO + bo, g1 + bo, be1 + bo, hin, n);
        ffn_ln_kernel<<<nb64, 256>>>(W1 + wo1, b1 + bo1, W2 + wo1, b2 + bo,
                                     g2 + bo, be2 + bo, hout, n);
    }
}

// round 10
// speedup vs baseline: 2.0544x; 1.0348x over previous
#include <cuda_runtime.h>
#include <cuda_bf16.h>
#include <cstdint>

#define NMAX 50000
#define EMAX 800000

// ---------------- scratch (device globals: no runtime allocation) -------------
__device__ float g_hA[NMAX * 64];   // layer-0 output / layer-1 input
__device__ float g_Q[NMAX * 64];
__device__ float g_K[NMAX * 64];
__device__ float g_V[NMAX * 64];
__device__ float g_wV[NMAX * 64];   // normalized attention output
__device__ float g_h1[NMAX * 64];
// CSR preprocessing
__device__ int   g_cnt[NMAX];       // degree, then running cursor
__device__ int   g_off2[NMAX + 1];  // exclusive prefix (CSR offsets)
__device__ int   g_psrc[EMAX];      // src node of permuted edge
__device__ int   g_ppos[EMAX];      // edge -> permuted position
__device__ float g_scp[EMAX * 4];   // scores in permuted order [pos][head]

// ---------------- CSR preprocessing (once per launch) --------------------------
__global__ void prep_zero(int n) {
    int i = blockIdx.x * blockDim.x + threadIdx.x;
    if (i < n) g_cnt[i] = 0;
}

__global__ void prep_hist(const int* __restrict__ ei, int ne) {
    int e = blockIdx.x * blockDim.x + threadIdx.x;
    if (e < ne) atomicAdd(&g_cnt[ei[ne + e]], 1);
}

// single-block exclusive scan: g_cnt (deg) -> g_off2 (excl), g_cnt := excl cursor
__global__ void prep_scan(int n) {
    __shared__ int wsum[32];
    __shared__ int carry_s;
    int tid = threadIdx.x, lane = tid & 31, w = tid >> 5;
    if (tid == 0) carry_s = 0;
    __syncthreads();
    for (int base = 0; base < n; base += 1024) {
        int i = base + tid;
        int v = (i < n) ? g_cnt[i] : 0;
        int s = v;
#pragma unroll
        for (int o = 1; o < 32; o <<= 1) {
            int t = __shfl_up_sync(0xffffffffu, s, o);
            if (lane >= o) s += t;
        }
        if (lane == 31) wsum[w] = s;
        __syncthreads();
        if (w == 0) {
            int ws = wsum[lane];
#pragma unroll
            for (int o = 1; o < 32; o <<= 1) {
                int t = __shfl_up_sync(0xffffffffu, ws, o);
                if (lane >= o) ws += t;
            }
            wsum[lane] = ws;
        }
        __syncthreads();
        int pre = (w > 0) ? wsum[w - 1] : 0;
        int excl = carry_s + pre + s - v;
        if (i < n) { g_off2[i] = excl; g_cnt[i] = excl; }
        __syncthreads();
        if (tid == 0) carry_s += wsum[31];
        __syncthreads();
    }
    if (tid == 0) g_off2[n] = carry_s;
}

__global__ void prep_scatter(const int* __restrict__ ei, int ne) {
    int e = blockIdx.x * blockDim.x + threadIdx.x;
    if (e < ne) {
        int d = ei[ne + e];
        int pos = atomicAdd(&g_cnt[d], 1);
        g_psrc[pos] = ei[e];
        g_ppos[e] = pos;
    }
}

// ---------------- bf16 3-term split GEMM machinery -----------------------------
__device__ __forceinline__ void split_store(uint32_t* hi, uint32_t* lo, int idx,
                                            float x, float y) {
    __nv_bfloat162 h = __floats2bfloat162_rn(x, y);
    float hx = __bfloat162float(h.x);
    float hy = __bfloat162float(h.y);
    __nv_bfloat162 l = __floats2bfloat162_rn(x - hx, y - hy);
    hi[idx] = *reinterpret_cast<uint32_t*>(&h);
    lo[idx] = *reinterpret_cast<uint32_t*>(&l);
}

__device__ __forceinline__ void mma16(float c[4], const uint32_t a[4], const uint32_t b[2]) {
    asm("mma.sync.aligned.m16n8k16.row.col.f32.bf16.bf16.f32 "
        "{%0,%1,%2,%3}, {%4,%5,%6,%7}, {%8,%9}, {%0,%1,%2,%3};"
        : "+f"(c[0]), "+f"(c[1]), "+f"(c[2]), "+f"(c[3])
        : "r"(a[0]), "r"(a[1]), "r"(a[2]), "r"(a[3]), "r"(b[0]), "r"(b[1]));
}

template<int AP, int WP>
__device__ __forceinline__ void gemm64_bf16(const uint32_t* __restrict__ Ahi,
                                            const uint32_t* __restrict__ Alo,
                                            const uint32_t* __restrict__ Whi,
                                            const uint32_t* __restrict__ Wlo,
                                            float acc[4][4], int r0, int n0) {
    int lane = threadIdx.x & 31;
    int g = lane >> 2, t4 = lane & 3;
#pragma unroll
    for (int kb = 0; kb < 32; kb += 8) {
        int ia0 = (r0 + g) * AP + kb + t4;
        int ia1 = (r0 + g + 8) * AP + kb + t4;
        uint32_t ah[4] = { Ahi[ia0], Ahi[ia1], Ahi[ia0 + 4], Ahi[ia1 + 4] };
        uint32_t al[4] = { Alo[ia0], Alo[ia1], Alo[ia0 + 4], Alo[ia1 + 4] };
#pragma unroll
        for (int nt = 0; nt < 4; ++nt) {
            int nn = n0 + nt * 8 + g;
            int ib0 = (kb + t4) * WP + nn;
            int ib1 = (kb + t4 + 4) * WP + nn;
            uint32_t bh[2] = { Whi[ib0], Whi[ib1] };
            uint32_t bl[2] = { Wlo[ib0], Wlo[ib1] };
            mma16(acc[nt], ah, bh);
            mma16(acc[nt], ah, bl);
            mma16(acc[nt], al, bh);
        }
    }
}

// smem word offsets (uint32 units)
#define A_HI 0
#define A_LO 2304      // 64*36
#define W_HI 4608
#define W_LO 6912      // + 32*72
#define SM_WORDS 9216

// ================= fused QKV GEMM =============================================
__global__ void qkvz_kernel(const float* __restrict__ A,
                            const float* __restrict__ WQ,
                            const float* __restrict__ WK,
                            const float* __restrict__ WV, int n) {
    __shared__ uint32_t sm[SM_WORDS];
    int row0 = blockIdx.x * 64;
    int tid = threadIdx.x;
    int w = tid >> 5, lane = tid & 31;
    int g = lane >> 2, t4 = lane & 3;
    int r0 = (w & 3) * 16, n0 = (w >> 2) * 32;

    for (int i = tid; i < 2048; i += 256) {
        int r = i >> 5, kp = i & 31;
        int gr = row0 + r;
        float2 v = (gr < n) ? *(const float2*)&A[(size_t)gr * 64 + kp * 2]
                            : make_float2(0.f, 0.f);
        split_store(sm + A_HI, sm + A_LO, r * 36 + kp, v.x, v.y);
    }

#pragma unroll
    for (int p = 0; p < 3; ++p) {
        const float* W = (p == 0) ? WQ : (p == 1) ? WK : WV;
        float* C = (p == 0) ? g_Q : (p == 1) ? g_K : g_V;
        __syncthreads();
        for (int i = tid; i < 2048; i += 256) {
            int kp = i >> 6, nn = i & 63;
            split_store(sm + W_HI, sm + W_LO, kp * 72 + nn,
                        W[(size_t)(2 * kp) * 64 + nn], W[(size_t)(2 * kp + 1) * 64 + nn]);
        }
        __syncthreads();

        float acc[4][4] = {};
        gemm64_bf16<36, 72>(sm + A_HI, sm + A_LO, sm + W_HI, sm + W_LO, acc, r0, n0);

#pragma unroll
        for (int nt = 0; nt < 4; ++nt) {
            int col = n0 + nt * 8 + t4 * 2;
#pragma unroll
            for (int ci = 0; ci < 2; ++ci) {
                int gr = row0 + r0 + g + 8 * ci;
                if (gr < n) {
                    float2 o = make_float2(acc[nt][ci * 2], acc[nt][ci * 2 + 1]);
                    *(float2*)&C[(size_t)gr * 64 + col] = o;
                }
            }
        }
    }
}

// ================= edge score kernel ==========================================
// Eh = edge_attr @ WE; score -> g_scp[ppos[e]*4+h]. No atomics, no V gather.
__global__ void edge_score_kernel(const float* __restrict__ Ae, const float* __restrict__ WE,
                                  const int* __restrict__ ei, int ne) {
    __shared__ uint32_t sm[SM_WORDS];
    __shared__ int s_src[64], s_dst[64];
    int e0 = blockIdx.x * 64;
    int tid = threadIdx.x;
    int w = tid >> 5, lane = tid & 31;
    int g = lane >> 2, t4 = lane & 3;
    int r0 = (w & 3) * 16, n0 = (w >> 2) * 32;

    for (int i = tid; i < 2048; i += 256) {
        int kp = i >> 6, nn = i & 63;
        split_store(sm + W_HI, sm + W_LO, kp * 72 + nn,
                    WE[(size_t)(2 * kp) * 64 + nn], WE[(size_t)(2 * kp + 1) * 64 + nn]);
    }
    for (int i = tid; i < 2048; i += 256) {
        int e = i >> 5, kp = i & 31;
        int ge = e0 + e;
        float2 v = (ge < ne) ? *(const float2*)&Ae[(size_t)ge * 64 + kp * 2]
                             : make_float2(0.f, 0.f);
        split_store(sm + A_HI, sm + A_LO, e * 36 + kp, v.x, v.y);
    }
    if (tid < 64) {
        int ge = e0 + tid;
        s_src[tid] = (ge < ne) ? ei[ge] : 0;
        s_dst[tid] = (ge < ne) ? ei[ne + ge] : 0;
    }
    __syncthreads();

    float acc[4][4] = {};
    gemm64_bf16<36, 72>(sm + A_HI, sm + A_LO, sm + W_HI, sm + W_LO, acc, r0, n0);
    __syncthreads();

    float* Ehs = (float*)(sm + A_HI);   // [64][68] floats
#pragma unroll
    for (int nt = 0; nt < 4; ++nt) {
        int col = n0 + nt * 8 + t4 * 2;
#pragma unroll
        for (int ci = 0; ci < 2; ++ci) {
            Ehs[(r0 + g + 8 * ci) * 68 + col]     = acc[nt][ci * 2];
            Ehs[(r0 + g + 8 * ci) * 68 + col + 1] = acc[nt][ci * 2 + 1];
        }
    }
    __syncthreads();

    // phase 2: one thread per (edge, head): score only
    int e = tid >> 2, h = tid & 3;
    int ge = e0 + e;
    if (ge < ne) {
        int sn = s_src[e], dn = s_dst[e];
        const float4* Kp = (const float4*)(g_K + (size_t)sn * 64 + h * 16);
        const float4* Qp = (const float4*)(g_Q + (size_t)dn * 64 + h * 16);
        float s = 0.f;
#pragma unroll
        for (int i = 0; i < 4; ++i) {
            float4 k4 = Kp[i];
            float4 q4 = Qp[i];
            const float* ep = &Ehs[e * 68 + h * 16 + i * 4];
            s += k4.x * q4.x * ep[0] + k4.y * q4.y * ep[1] +
                 k4.z * q4.z * ep[2] + k4.w * q4.w * ep[3];
        }
        s *= 0.25f;                        // 1/sqrt(16)
        s = fminf(fmaxf(s, -5.f), 5.f);
        float sc = __expf(s);
        int pos = g_ppos[ge];
        g_scp[(size_t)pos * 4 + h] = sc;
    }
}

// ================= aggregation: warp per dst node ==============================
// g_wV[dst] = (sum_e sc * V[src]) / (sum_e sc + 1e-6), per head
__global__ void agg_kernel(int n) {
    int node = (blockIdx.x * 256 + threadIdx.x) >> 5;
    int lane = threadIdx.x & 31;
    if (node >= n) return;
    int beg = g_off2[node], end = g_off2[node + 1];
    int h = lane >> 3;                    // head for cols [lane*2, lane*2+1]
    float ax = 0.f, ay = 0.f, z = 0.f;
    for (int p = beg; p < end; ++p) {
        int sn = g_psrc[p];               // sequential (L1)
        float sc = g_scp[(size_t)p * 4 + h];  // sequential (L1)
        float2 v = *(const float2*)&g_V[(size_t)sn * 64 + lane * 2];  // random row, coalesced
        ax += sc * v.x; ay += sc * v.y; z += sc;
    }
    float inv = 1.f / (z + 1e-6f);
    *(float2*)&g_wV[(size_t)node * 64 + lane * 2] = make_float2(ax * inv, ay * inv);
}

// ================= attn out-proj + residual + LayerNorm1 ======================
__global__ void attn_ln_kernel(const float* __restrict__ WO, const float* __restrict__ bO,
                               const float* __restrict__ g1, const float* __restrict__ be,
                               const float* __restrict__ hin, int n) {
    __shared__ uint32_t sm[SM_WORDS];
    int row0 = blockIdx.x * 64;
    int tid = threadIdx.x;
    int w = tid >> 5, lane = tid & 31;
    int g = lane >> 2, t4 = lane & 3;
    int r0 = (w & 3) * 16, n0 = (w >> 2) * 32;

    for (int i = tid; i < 2048; i += 256) {
        int kp = i >> 6, nn = i & 63;
        split_store(sm + W_HI, sm + W_LO, kp * 72 + nn,
                    WO[(size_t)(2 * kp) * 64 + nn], WO[(size_t)(2 * kp + 1) * 64 + nn]);
    }
    for (int i = tid; i < 2048; i += 256) {
        int r = i >> 5, kp = i & 31;
        int gr = row0 + r;
        float2 v = (gr < n) ? *(const float2*)&g_wV[(size_t)gr * 64 + kp * 2]
                            : make_float2(0.f, 0.f);
        split_store(sm + A_HI, sm + A_LO, r * 36 + kp, v.x, v.y);
    }
    __syncthreads();

    float acc[4][4] = {};
    gemm64_bf16<36, 72>(sm + A_HI, sm + A_LO, sm + W_HI, sm + W_LO, acc, r0, n0);
    __syncthreads();

    float* ts = (float*)(sm + A_HI);   // [64][68]
#pragma unroll
    for (int nt = 0; nt < 4; ++nt) {
        int col = n0 + nt * 8 + t4 * 2;
        float2 bb = *(const float2*)&bO[col];
#pragma unroll
        for (int ci = 0; ci < 2; ++ci) {
            int r = r0 + g + 8 * ci;
            int gr = row0 + r;
            if (gr < n) {
                float2 h4 = *(const float2*)&hin[(size_t)gr * 64 + col];
                ts[r * 68 + col]     = h4.x + acc[nt][ci * 2]     + bb.x;
                ts[r * 68 + col + 1] = h4.y + acc[nt][ci * 2 + 1] + bb.y;
            }
        }
    }
    __syncthreads();

    for (int i = 0; i < 8; ++i) {
        int r = w * 8 + i;
        int gr = row0 + r;
        if (gr >= n) break;
        float x0 = ts[r * 68 + lane], x1 = ts[r * 68 + lane + 32];
        float s = x0 + x1;
#pragma unroll
        for (int o = 16; o; o >>= 1) s += __shfl_xor_sync(0xffffffffu, s, o);
        float mu = s * (1.f / 64.f);
        float d0 = x0 - mu, d1 = x1 - mu;
        float v = d0 * d0 + d1 * d1;
#pragma unroll
        for (int o = 16; o; o >>= 1) v += __shfl_xor_sync(0xffffffffu, v, o);
        float inv = rsqrtf(v * (1.f / 64.f) + 1e-5f);
        g_h1[(size_t)gr * 64 + lane]      = d0 * inv * g1[lane] + be[lane];
        g_h1[(size_t)gr * 64 + lane + 32] = d1 * inv * g1[lane + 32] + be[lane + 32];
    }
}

// ================= fused FFN + residual + LayerNorm2 ==========================
__global__ void ffn_ln_kernel(const float* __restrict__ W1, const float* __restrict__ b1,
                              const float* __restrict__ W2, const float* __restrict__ b2,
                              const float* __restrict__ g1, const float* __restrict__ be,
                              float* __restrict__ hout, int n) {
    __shared__ uint32_t sm[13824];
    uint32_t* H_HIp = sm;
    uint32_t* H_LOp = sm + 2304;
    uint32_t* U_HIp = sm + 4608;
    uint32_t* U_LOp = sm + 6912;
    uint32_t* Wk_HI = sm + 9216;
    uint32_t* Wk_LO = sm + 11520;
    int row0 = blockIdx.x * 64;
    int tid = threadIdx.x;
    int w = tid >> 5, lane = tid & 31;
    int g = lane >> 2, t4 = lane & 3;
    int r0 = (w & 3) * 16, n0 = (w >> 2) * 32;

    for (int i = tid; i < 2048; i += 256) {
        int r = i >> 5, kp = i & 31;
        int gr = row0 + r;
        float2 v = (gr < n) ? *(const float2*)&g_h1[(size_t)gr * 64 + kp * 2]
                            : make_float2(0.f, 0.f);
        split_store(H_HIp, H_LOp, r * 36 + kp, v.x, v.y);
    }

    float acc2[4][4] = {};
#pragma unroll
    for (int kk = 0; kk < 2; ++kk) {
        __syncthreads();
        for (int i = tid; i < 2048; i += 256) {
            int kp = i >> 6, nn = i & 63;
            split_store(Wk_HI, Wk_LO, kp * 72 + nn,
                        W1[(size_t)(2 * kp) * 128 + kk * 64 + nn],
                        W1[(size_t)(2 * kp + 1) * 128 + kk * 64 + nn]);
        }
        __syncthreads();

        float acc[4][4] = {};
        gemm64_bf16<36, 72>(H_HIp, H_LOp, Wk_HI, Wk_LO, acc, r0, n0);

#pragma unroll
        for (int nt = 0; nt < 4; ++nt) {
            int col = n0 + nt * 8 + t4 * 2;
            float2 bb = *(const float2*)&b1[kk * 64 + col];
            int cp = col >> 1;
#pragma unroll
            for (int ci = 0; ci < 2; ++ci) {
                int r = r0 + g + 8 * ci;
                float u0 = fmaxf(acc[nt][ci * 2]     + bb.x, 0.f);
                float u1 = fmaxf(acc[nt][ci * 2 + 1] + bb.y, 0.f);
                split_store(U_HIp, U_LOp, r * 36 + cp, u0, u1);
            }
        }
        __syncthreads();
        for (int i = tid; i < 2048; i += 256) {
            int kp = i >> 6, nn = i & 63;
            split_store(Wk_HI, Wk_LO, kp * 72 + nn,
                        W2[(size_t)(kk * 64 + 2 * kp) * 64 + nn],
                        W2[(size_t)(kk * 64 + 2 * kp + 1) * 64 + nn]);
        }
        __syncthreads();

        gemm64_bf16<36, 72>(U_HIp, U_LOp, Wk_HI, Wk_LO, acc2, r0, n0);
    }
    __syncthreads();

    float* ts = (float*)U_HIp;   // [64][68]
#pragma unroll
    for (int nt = 0; nt < 4; ++nt) {
        int col = n0 + nt * 8 + t4 * 2;
        float2 bb = *(const float2*)&b2[col];
        int cp = col >> 1;
#pragma unroll
        for (int ci = 0; ci < 2; ++ci) {
            int r = r0 + g + 8 * ci;
            uint32_t hw = H_HIp[r * 36 + cp], lw = H_LOp[r * 36 + cp];
            __nv_bfloat162 hh = *reinterpret_cast<__nv_bfloat162*>(&hw);
            __nv_bfloat162 ll = *reinterpret_cast<__nv_bfloat162*>(&lw);
            float h0 = __bfloat162float(hh.x) + __bfloat162float(ll.x);
            float h1v = __bfloat162float(hh.y) + __bfloat162float(ll.y);
            ts[r * 68 + col]     = h0  + acc2[nt][ci * 2]     + bb.x;
            ts[r * 68 + col + 1] = h1v + acc2[nt][ci * 2 + 1] + bb.y;
        }
    }
    __syncthreads();

    for (int i = 0; i < 8; ++i) {
        int r = w * 8 + i;
        int gr = row0 + r;
        if (gr >= n) break;
        float x0 = ts[r * 68 + lane], x1 = ts[r * 68 + lane + 32];
        float s = x0 + x1;
#pragma unroll
        for (int o = 16; o; o >>= 1) s += __shfl_xor_sync(0xffffffffu, s, o);
        float mu = s * (1.f / 64.f);
        float d0 = x0 - mu, d1 = x1 - mu;
        float v = d0 * d0 + d1 * d1;
#pragma unroll
        for (int o = 16; o; o >>= 1) v += __shfl_xor_sync(0xffffffffu, v, o);
        float inv = rsqrtf(v * (1.f / 64.f) + 1e-5f);
        hout[(size_t)gr * 64 + lane]      = d0 * inv * g1[lane] + be[lane];
        hout[(size_t)gr * 64 + lane + 32] = d1 * inv * g1[lane + 32] + be[lane + 32];
    }
}

// ---------------- host orchestration ------------------------------------------
extern "C" void kernel_launch(void* const* d_in, const int* in_sizes, int n_in,
                              void* d_out, int out_size) {
    const float* x   = (const float*)d_in[0];
    const float* ea  = (const float*)d_in[1];
    const int*   ei  = (const int*)d_in[2];   // int32 per harness dtype rules
    const float* WQ  = (const float*)d_in[3];
    const float* WK  = (const float*)d_in[4];
    const float* WE  = (const float*)d_in[5];
    const float* WV  = (const float*)d_in[6];
    const float* WO  = (const float*)d_in[7];
    const float* bO  = (const float*)d_in[8];
    const float* g1  = (const float*)d_in[9];
    const float* be1 = (const float*)d_in[10];
    const float* W1  = (const float*)d_in[11];
    const float* b1  = (const float*)d_in[12];
    const float* W2  = (const float*)d_in[13];
    const float* b2  = (const float*)d_in[14];
    const float* g2  = (const float*)d_in[15];
    const float* be2 = (const float*)d_in[16];
    float* out = (float*)d_out;

    int n  = in_sizes[0] / 64;
    int ne = in_sizes[2] / 2;

    float* p_hA;
    cudaGetSymbolAddress((void**)&p_hA, g_hA);

    int nb64 = (n + 63) / 64;
    int nbe  = (ne + 63) / 64;

    // ---- CSR preprocessing (once) ----
    prep_zero<<<(n + 255) / 256, 256>>>(n);
    prep_hist<<<(ne + 255) / 256, 256>>>(ei, ne);
    prep_scan<<<1, 1024>>>(n);
    prep_scatter<<<(ne + 255) / 256, 256>>>(ei, ne);

    for (int l = 0; l < 2; ++l) {
        const float* hin  = l ? p_hA : x;
        float*       hout = l ? out : p_hA;
        size_t wo  = (size_t)l * 64 * 64;
        size_t wo1 = (size_t)l * 64 * 128;
        size_t bo  = (size_t)l * 64;
        size_t bo1 = (size_t)l * 128;

        qkvz_kernel<<<nb64, 256>>>(hin, WQ + wo, WK + wo, WV + wo, n);
        edge_score_kernel<<<nbe, 256>>>(ea, WE + wo, ei, ne);
        agg_kernel<<<(n * 32 + 255) / 256, 256>>>(n);
        attn_ln_kernel<<<nb64, 256>>>(WO + wo, bO + bo, g1 + bo, be1 + bo, hin, n);
        ffn_ln_kernel<<<nb64, 256>>>(W1 + wo1, b1 + bo1, W2 + wo1, b2 + bo,
                                     g2 + bo, be2 + bo, hout, n);
    }
}